// round 3
// baseline (speedup 1.0000x reference)
#include <cuda_runtime.h>
#include <math.h>

#define BATCH 4096
#define NCOL  7
#define DIM   1024
#define DIM2  2048
#define MROWS (BATCH*NCOL)      // 28672
#define NITER 3
#define MD    ((long long)MROWS * DIM)   // 29,360,128

// ---------------- scratch (static device globals; no allocations) ----------
__device__ float g_cur   [(size_t)MROWS * DIM];
__device__ float g_h1    [(size_t)MROWS * DIM2];
__device__ float g_err   [(size_t)MROWS * DIM];
__device__ float g_errsum[(size_t)MROWS * DIM];
__device__ float g_fb    [(size_t)MROWS * DIM];
__device__ float g_fbk   [(size_t)MROWS * DIM];
__device__ float g_gain  [(size_t)MROWS * DIM];

__device__ __forceinline__ float gelu_exact(float x) {
    return 0.5f * x * (1.0f + erff(x * 0.7071067811865476f));
}
__device__ __forceinline__ float sigmoid_(float x) {
    return 1.0f / (1.0f + expf(-x));
}

// Epilogue variants
#define EPI_GELU 0
#define EPI_BIAS 1
#define EPI_ERR  2
#define EPI_SIG  3
#define EPI_UPD  4

// C[M,N] = A[M,K] * W[N,K]^T + bias[N], with fused epilogues.
// Virtual concat along K: k < Ksplit reads A1, else A2 (same ldA).
// z-batched via aZ/wZ/bZ/cZ element offsets (colony-batched cb GEMM).
// All M,N multiples of 128 and K multiples of 8 -> no bounds checks.
template<int EPI>
__global__ __launch_bounds__(256, 2)
void gemm_k(const float* __restrict__ A1, const float* __restrict__ A2,
            int Ksplit, int ldA,
            const float* __restrict__ W,
            const float* __restrict__ bias,
            float* __restrict__ Cout, int ldC,
            int K,
            long long aZ, long long wZ, long long bZ, long long cZ,
            const float* __restrict__ bu, float* __restrict__ errsum,
            const float* __restrict__ gain, const float* __restrict__ fs)
{
    __shared__ float As[8][128];
    __shared__ float Ws[8][128];

    const int z = blockIdx.z;
    A1 += z * aZ; A2 += z * aZ; W += z * wZ; bias += z * bZ; Cout += z * cZ;

    const int row0 = blockIdx.y * 128;
    const int col0 = blockIdx.x * 128;
    const int tid  = threadIdx.x;
    const int ty = tid >> 4, tx = tid & 15;
    const int lr = tid >> 1;            // 0..127
    const int lc = (tid & 1) * 4;       // 0 or 4

    float acc[8][8];
    #pragma unroll
    for (int i = 0; i < 8; i++)
        #pragma unroll
        for (int j = 0; j < 8; j++) acc[i][j] = 0.f;

    const float* wrow = W + (long long)(col0 + lr) * K + lc;

    for (int k0 = 0; k0 < K; k0 += 8) {
        const float* asrc = (k0 < Ksplit)
            ? (A1 + (long long)(row0 + lr) * ldA + k0 + lc)
            : (A2 + (long long)(row0 + lr) * ldA + (k0 - Ksplit) + lc);
        float4 av = *(const float4*)asrc;
        float4 wv = *(const float4*)(wrow + k0);
        __syncthreads();
        As[lc+0][lr]=av.x; As[lc+1][lr]=av.y; As[lc+2][lr]=av.z; As[lc+3][lr]=av.w;
        Ws[lc+0][lr]=wv.x; Ws[lc+1][lr]=wv.y; Ws[lc+2][lr]=wv.z; Ws[lc+3][lr]=wv.w;
        __syncthreads();
        #pragma unroll
        for (int kk = 0; kk < 8; kk++) {
            float a[8], b[8];
            *(float4*)&a[0] = *(const float4*)&As[kk][ty*8];
            *(float4*)&a[4] = *(const float4*)&As[kk][ty*8+4];
            *(float4*)&b[0] = *(const float4*)&Ws[kk][tx*8];
            *(float4*)&b[4] = *(const float4*)&Ws[kk][tx*8+4];
            #pragma unroll
            for (int i = 0; i < 8; i++)
                #pragma unroll
                for (int j = 0; j < 8; j++)
                    acc[i][j] = fmaf(a[i], b[j], acc[i][j]);
        }
    }

    #pragma unroll
    for (int i = 0; i < 8; i++) {
        const int r = row0 + ty * 8 + i;
        float fsc = 0.f;
        if (EPI == EPI_UPD) fsc = fs[r % NCOL] * (5.0f / 3.0f);
        #pragma unroll
        for (int j4 = 0; j4 < 2; j4++) {
            const int n = col0 + tx * 8 + j4 * 4;
            const long long idx = (long long)r * ldC + n;
            float4 bb = *(const float4*)(bias + n);
            float4 v;
            v.x = acc[i][j4*4+0] + bb.x;
            v.y = acc[i][j4*4+1] + bb.y;
            v.z = acc[i][j4*4+2] + bb.z;
            v.w = acc[i][j4*4+3] + bb.w;
            if (EPI == EPI_GELU) {
                v.x = gelu_exact(v.x); v.y = gelu_exact(v.y);
                v.z = gelu_exact(v.z); v.w = gelu_exact(v.w);
                *(float4*)(Cout + idx) = v;
            } else if (EPI == EPI_BIAS) {
                *(float4*)(Cout + idx) = v;
            } else if (EPI == EPI_SIG) {
                v.x = sigmoid_(v.x); v.y = sigmoid_(v.y);
                v.z = sigmoid_(v.z); v.w = sigmoid_(v.w);
                *(float4*)(Cout + idx) = v;
            } else if (EPI == EPI_ERR) {
                float4 u = *(const float4*)(bu + idx);
                float4 e = make_float4(u.x - v.x, u.y - v.y, u.z - v.z, u.w - v.w);
                *(float4*)(Cout + idx) = e;
                float4 s = *(float4*)(errsum + idx);
                s.x += e.x; s.y += e.y; s.z += e.z; s.w += e.w;
                *(float4*)(errsum + idx) = s;
            } else { // EPI_UPD: current += (acc+bias)*gain*fs[c]*(5/3)
                float4 gv = *(const float4*)(gain + idx);
                float4 c  = *(float4*)(Cout + idx);
                c.x += v.x * gv.x * fsc;
                c.y += v.y * gv.y * fsc;
                c.z += v.z * gv.z * fsc;
                c.w += v.w * gv.w * fsc;
                *(float4*)(Cout + idx) = c;
            }
        }
    }
}

// cur = hidden_states; errsum = 0
__global__ void init_k(const float4* __restrict__ hs, float4* __restrict__ cur,
                       float4* __restrict__ errsum, long long n4)
{
    long long i = (long long)blockIdx.x * blockDim.x + threadIdx.x;
    if (i < n4) { cur[i] = hs[i]; errsum[i] = make_float4(0.f, 0.f, 0.f, 0.f); }
}

// Fano mask == ones(7,7)-I: feedback[b,i,:] = sum_j fb[b,j,:] - fb[b,i,:]
__global__ void feedback_k(const float* __restrict__ fb, float* __restrict__ fbk)
{
    const long long n4 = (long long)BATCH * DIM / 4;
    long long i = (long long)blockIdx.x * blockDim.x + threadIdx.x;
    if (i >= n4) return;
    long long b = i / (DIM / 4);
    long long d = i % (DIM / 4);
    const float4* f = (const float4*)fb;
    float4* o = (float4*)fbk;
    float4 v[NCOL];
    float4 s = make_float4(0.f, 0.f, 0.f, 0.f);
    #pragma unroll
    for (int j = 0; j < NCOL; j++) {
        v[j] = f[(b * NCOL + j) * (DIM / 4) + d];
        s.x += v[j].x; s.y += v[j].y; s.z += v[j].z; s.w += v[j].w;
    }
    #pragma unroll
    for (int j = 0; j < NCOL; j++)
        o[(b * NCOL + j) * (DIM / 4) + d] =
            make_float4(s.x - v[j].x, s.y - v[j].y, s.z - v[j].z, s.w - v[j].w);
}

// out = [current | feedback | errsum/3 | feedback_strength]
__global__ void final_k(const float4* __restrict__ cur, const float4* __restrict__ fbk,
                        const float4* __restrict__ errsum, const float* __restrict__ fs,
                        float* __restrict__ out)
{
    const long long n4 = MD / 4;
    long long i = (long long)blockIdx.x * blockDim.x + threadIdx.x;
    float4* o4 = (float4*)out;
    if (i < n4) {
        o4[i] = cur[i];
    } else if (i < 2 * n4) {
        o4[i] = fbk[i - n4];
    } else if (i < 3 * n4) {
        float4 e = errsum[i - 2 * n4];
        o4[i] = make_float4(e.x * (1.f/3.f), e.y * (1.f/3.f),
                            e.z * (1.f/3.f), e.w * (1.f/3.f));
    }
    if (i < NCOL) out[3 * MD + i] = fs[i];
}

extern "C" void kernel_launch(void* const* d_in, const int* in_sizes, int n_in,
                              void* d_out, int out_size)
{
    const float* hs  = (const float*)d_in[0];
    const float* bu  = (const float*)d_in[1];
    const float* cbW = (const float*)d_in[2];
    const float* cbB = (const float*)d_in[3];
    const float* p1W = (const float*)d_in[4];
    const float* p1b = (const float*)d_in[5];
    const float* p2W = (const float*)d_in[6];
    const float* p2b = (const float*)d_in[7];
    const float* e1W = (const float*)d_in[8];
    const float* e1b = (const float*)d_in[9];
    const float* e2W = (const float*)d_in[10];
    const float* e2b = (const float*)d_in[11];
    const float* gW  = (const float*)d_in[12];
    const float* gb  = (const float*)d_in[13];
    const float* fs  = (const float*)d_in[14];
    float* out = (float*)d_out;

    float *cur, *h1, *err, *errsum, *fb, *fbk, *gainb;
    cudaGetSymbolAddress((void**)&cur,    g_cur);
    cudaGetSymbolAddress((void**)&h1,     g_h1);
    cudaGetSymbolAddress((void**)&err,    g_err);
    cudaGetSymbolAddress((void**)&errsum, g_errsum);
    cudaGetSymbolAddress((void**)&fb,     g_fb);
    cudaGetSymbolAddress((void**)&fbk,    g_fbk);
    cudaGetSymbolAddress((void**)&gainb,  g_gain);

    const long long n4 = MD / 4;
    init_k<<<(unsigned)((n4 + 255) / 256), 256>>>((const float4*)hs, (float4*)cur,
                                                  (float4*)errsum, n4);

    dim3 gP1(DIM2 / 128, MROWS / 128, 1);   // 16 x 224
    dim3 gD (DIM  / 128, MROWS / 128, 1);   //  8 x 224
    dim3 gCB(DIM  / 128, BATCH / 128, NCOL);//  8 x 32 x 7

    for (int it = 0; it < NITER; it++) {
        // h1 = gelu(cur @ p1_W^T + p1_b)            [M,2048]
        gemm_k<EPI_GELU><<<gP1, 256>>>(cur, cur, DIM, DIM, p1W, p1b, h1, DIM2, DIM,
                                       0, 0, 0, 0, nullptr, nullptr, nullptr, nullptr);
        // err = bu - (h1 @ p2_W^T + p2_b); errsum += err
        gemm_k<EPI_ERR><<<gD, 256>>>(h1, h1, DIM2, DIM2, p2W, p2b, err, DIM, DIM2,
                                     0, 0, 0, 0, bu, errsum, nullptr, nullptr);
        // fb[:,j,:] = cur[:,j,:] @ cb_W[j]^T + cb_b[j]   (z-batched over colony)
        gemm_k<EPI_BIAS><<<gCB, 256>>>(cur, cur, DIM, NCOL * DIM, cbW, cbB,
                                       fb, NCOL * DIM, DIM,
                                       (long long)DIM, (long long)DIM * DIM,
                                       (long long)DIM, (long long)DIM,
                                       nullptr, nullptr, nullptr, nullptr);
        // feedback = rowsum(fb) - fb   (Fano mask == ones - I)
        feedback_k<<<(unsigned)(((long long)BATCH * DIM / 4 + 255) / 256), 256>>>(fb, fbk);
        // gain = sigmoid([cur|fbk] @ g_W^T + g_b)   (virtual concat over K)
        gemm_k<EPI_SIG><<<gD, 256>>>(cur, fbk, DIM, DIM, gW, gb, gainb, DIM, DIM2,
                                     0, 0, 0, 0, nullptr, nullptr, nullptr, nullptr);
        // pe1 = gelu(err @ e1_W^T + e1_b)  (reuse h1 as [M,1024] scratch)
        gemm_k<EPI_GELU><<<gD, 256>>>(err, err, DIM, DIM, e1W, e1b, h1, DIM, DIM,
                                      0, 0, 0, 0, nullptr, nullptr, nullptr, nullptr);
        // cur += (pe1 @ e2_W^T + e2_b) * gain * fs[c] * (5/3)
        gemm_k<EPI_UPD><<<gD, 256>>>(h1, h1, DIM, DIM, e2W, e2b, cur, DIM, DIM,
                                     0, 0, 0, 0, nullptr, nullptr, gainb, fs);
    }

    final_k<<<(unsigned)((3 * n4 + 255) / 256), 256>>>((const float4*)cur,
                                                       (const float4*)fbk,
                                                       (const float4*)errsum, fs, out);
}

// round 5
// speedup vs baseline: 5.4077x; 5.4077x over previous
#include <cuda_runtime.h>
#include <math.h>
#include <stdint.h>

#define BATCH 4096
#define NCOL  7
#define DIM   1024
#define DIM2  2048
#define MROWS (BATCH*NCOL)      // 28672
#define NITER 3
#define MD    ((long long)MROWS * DIM)

// ---------------- scratch (static device globals; no allocations) ----------
__device__ float g_cur   [(size_t)MROWS * DIM];
__device__ float g_h1    [(size_t)MROWS * DIM2];
__device__ float g_err   [(size_t)MROWS * DIM];
__device__ float g_errsum[(size_t)MROWS * DIM];
__device__ float g_fb    [(size_t)MROWS * DIM];
__device__ float g_fbk   [(size_t)MROWS * DIM];
__device__ float g_gain  [(size_t)MROWS * DIM];

__device__ __forceinline__ float gelu_exact(float x) {
    return 0.5f * x * (1.0f + erff(x * 0.7071067811865476f));
}
__device__ __forceinline__ float sigmoid_(float x) {
    return 1.0f / (1.0f + expf(-x));
}
__device__ __forceinline__ uint32_t f2tf(float f) {
    uint32_t u;
    asm("cvt.rna.tf32.f32 %0, %1;" : "=r"(u) : "f"(f));
    return u;
}

#define EPI_GELU 0
#define EPI_BIAS 1
#define EPI_ERR  2
#define EPI_SIG  3
#define EPI_UPD  4

// padded smem row stride in floats: 20*4B = 80B (16B-aligned rows, and the
// m16n8k8 fragment gather pattern (bank = (20*r + c) mod 32) is conflict-free)
#define LDS_PAD 20

// C[M,N] = A[M,K] * W[N,K]^T + bias[N], tf32 tensor-core version.
// Virtual concat along K: k < Ksplit reads A1, else A2.
// z-batched via aZ/wZ/bZ/cZ element offsets.
// M,N multiples of 128; K multiple of 16.
template<int EPI>
__global__ __launch_bounds__(256)
void gemm_tc(const float* __restrict__ A1, const float* __restrict__ A2,
             int Ksplit, int ldA,
             const float* __restrict__ W,
             const float* __restrict__ bias,
             float* __restrict__ Cout, int ldC,
             int K,
             long long aZ, long long wZ, long long bZ, long long cZ,
             const float* __restrict__ bu, float* __restrict__ errsum,
             const float* __restrict__ gain, const float* __restrict__ fs)
{
    __shared__ float As[2][128 * LDS_PAD];
    __shared__ float Bs[2][128 * LDS_PAD];

    const int z = blockIdx.z;
    A1 += z * aZ; A2 += z * aZ; W += z * wZ; bias += z * bZ; Cout += z * cZ;

    const int row0 = blockIdx.y * 128;
    const int col0 = blockIdx.x * 128;
    const int tid  = threadIdx.x;
    const int warp = tid >> 5, lane = tid & 31;
    const int wm = (warp >> 2) * 64;   // warp row offset in tile (0 or 64)
    const int wn = (warp & 3) * 32;    // warp col offset in tile (0..96)
    const int lr4 = lane >> 2;         // 0..7
    const int lc4 = lane & 3;          // 0..3

    float acc[4][4][4];
    #pragma unroll
    for (int a = 0; a < 4; a++)
        #pragma unroll
        for (int b = 0; b < 4; b++)
            #pragma unroll
            for (int c = 0; c < 4; c++) acc[a][b][c] = 0.f;

    uint32_t sA = (uint32_t)__cvta_generic_to_shared(&As[0][0]);
    uint32_t sB = (uint32_t)__cvta_generic_to_shared(&Bs[0][0]);

    const int NC = K / 16;  // number of k-chunks

    // ---- async chunk loader: chunk cidx -> buffer buf ----
    auto load_chunk = [&](int cidx, int buf) {
        const int k0 = cidx * 16;
        const float* Abase;
        int kk;
        if (k0 < Ksplit) { Abase = A1; kk = k0; }
        else             { Abase = A2; kk = k0 - Ksplit; }
        #pragma unroll
        for (int i = 0; i < 2; i++) {
            const int q  = tid + i * 256;      // 0..511
            const int r  = q >> 2;             // row 0..127
            const int cc = q & 3;              // 16B chunk 0..3
            uint32_t da = sA + (uint32_t)(buf * 128 * LDS_PAD + r * LDS_PAD + cc * 4) * 4u;
            const float* ga = Abase + (long long)(row0 + r) * ldA + kk + cc * 4;
            asm volatile("cp.async.cg.shared.global [%0], [%1], 16;\n" :: "r"(da), "l"(ga));
            uint32_t db = sB + (uint32_t)(buf * 128 * LDS_PAD + r * LDS_PAD + cc * 4) * 4u;
            const float* gb = W + (long long)(col0 + r) * K + k0 + cc * 4;
            asm volatile("cp.async.cg.shared.global [%0], [%1], 16;\n" :: "r"(db), "l"(gb));
        }
        asm volatile("cp.async.commit_group;\n");
    };

    load_chunk(0, 0);

    for (int c = 0; c < NC; c++) {
        const int buf = c & 1;
        if (c + 1 < NC) {
            load_chunk(c + 1, buf ^ 1);
            asm volatile("cp.async.wait_group 1;\n");
        } else {
            asm volatile("cp.async.wait_group 0;\n");
        }
        __syncthreads();

        const float* Ab = &As[buf][0];
        const float* Bb = &Bs[buf][0];

        #pragma unroll
        for (int kt = 0; kt < 2; kt++) {
            uint32_t af[4][4], bf[4][2];
            const int kc = kt * 8 + lc4;
            #pragma unroll
            for (int mt = 0; mt < 4; mt++) {
                const int r = wm + mt * 16 + lr4;
                af[mt][0] = f2tf(Ab[r       * LDS_PAD + kc    ]);
                af[mt][1] = f2tf(Ab[(r + 8) * LDS_PAD + kc    ]);
                af[mt][2] = f2tf(Ab[r       * LDS_PAD + kc + 4]);
                af[mt][3] = f2tf(Ab[(r + 8) * LDS_PAD + kc + 4]);
            }
            #pragma unroll
            for (int nt = 0; nt < 4; nt++) {
                const int r = wn + nt * 8 + lr4;
                bf[nt][0] = f2tf(Bb[r * LDS_PAD + kc    ]);
                bf[nt][1] = f2tf(Bb[r * LDS_PAD + kc + 4]);
            }
            #pragma unroll
            for (int mt = 0; mt < 4; mt++)
                #pragma unroll
                for (int nt = 0; nt < 4; nt++) {
                    asm volatile(
                        "mma.sync.aligned.m16n8k8.row.col.f32.tf32.tf32.f32 "
                        "{%0,%1,%2,%3}, {%4,%5,%6,%7}, {%8,%9}, {%0,%1,%2,%3};\n"
                        : "+f"(acc[mt][nt][0]), "+f"(acc[mt][nt][1]),
                          "+f"(acc[mt][nt][2]), "+f"(acc[mt][nt][3])
                        : "r"(af[mt][0]), "r"(af[mt][1]), "r"(af[mt][2]), "r"(af[mt][3]),
                          "r"(bf[nt][0]), "r"(bf[nt][1]));
                }
        }
        __syncthreads();
    }

    // ---- epilogue: accumulator layout m16n8: rows {lr4, lr4+8}, cols {2*lc4, 2*lc4+1}
    #pragma unroll
    for (int mt = 0; mt < 4; mt++) {
        #pragma unroll
        for (int h = 0; h < 2; h++) {
            const int r = row0 + wm + mt * 16 + lr4 + h * 8;
            float fsc = 0.f;
            if (EPI == EPI_UPD) fsc = fs[r % NCOL] * (5.0f / 3.0f);
            #pragma unroll
            for (int nt = 0; nt < 4; nt++) {
                const int n = col0 + wn + nt * 8 + 2 * lc4;
                const long long idx = (long long)r * ldC + n;
                float2 bb = *(const float2*)(bias + n);
                float2 v;
                v.x = acc[mt][nt][h * 2 + 0] + bb.x;
                v.y = acc[mt][nt][h * 2 + 1] + bb.y;
                if (EPI == EPI_GELU) {
                    v.x = gelu_exact(v.x); v.y = gelu_exact(v.y);
                    *(float2*)(Cout + idx) = v;
                } else if (EPI == EPI_BIAS) {
                    *(float2*)(Cout + idx) = v;
                } else if (EPI == EPI_SIG) {
                    v.x = sigmoid_(v.x); v.y = sigmoid_(v.y);
                    *(float2*)(Cout + idx) = v;
                } else if (EPI == EPI_ERR) {
                    float2 u = *(const float2*)(bu + idx);
                    float2 e = make_float2(u.x - v.x, u.y - v.y);
                    *(float2*)(Cout + idx) = e;
                    float2 s = *(float2*)(errsum + idx);
                    s.x += e.x; s.y += e.y;
                    *(float2*)(errsum + idx) = s;
                } else { // EPI_UPD
                    float2 gv = *(const float2*)(gain + idx);
                    float2 cc = *(float2*)(Cout + idx);
                    cc.x += v.x * gv.x * fsc;
                    cc.y += v.y * gv.y * fsc;
                    *(float2*)(Cout + idx) = cc;
                }
            }
        }
    }
}

// cur = hidden_states; errsum = 0
__global__ void init_k(const float4* __restrict__ hs, float4* __restrict__ cur,
                       float4* __restrict__ errsum, long long n4)
{
    long long i = (long long)blockIdx.x * blockDim.x + threadIdx.x;
    if (i < n4) { cur[i] = hs[i]; errsum[i] = make_float4(0.f, 0.f, 0.f, 0.f); }
}

// Fano mask == ones(7,7)-I: feedback[b,i,:] = sum_j fb[b,j,:] - fb[b,i,:]
__global__ void feedback_k(const float* __restrict__ fb, float* __restrict__ fbk)
{
    const long long n4 = (long long)BATCH * DIM / 4;
    long long i = (long long)blockIdx.x * blockDim.x + threadIdx.x;
    if (i >= n4) return;
    long long b = i / (DIM / 4);
    long long d = i % (DIM / 4);
    const float4* f = (const float4*)fb;
    float4* o = (float4*)fbk;
    float4 v[NCOL];
    float4 s = make_float4(0.f, 0.f, 0.f, 0.f);
    #pragma unroll
    for (int j = 0; j < NCOL; j++) {
        v[j] = f[(b * NCOL + j) * (DIM / 4) + d];
        s.x += v[j].x; s.y += v[j].y; s.z += v[j].z; s.w += v[j].w;
    }
    #pragma unroll
    for (int j = 0; j < NCOL; j++)
        o[(b * NCOL + j) * (DIM / 4) + d] =
            make_float4(s.x - v[j].x, s.y - v[j].y, s.z - v[j].z, s.w - v[j].w);
}

// out = [current | feedback | errsum/3 | feedback_strength]
__global__ void final_k(const float4* __restrict__ cur, const float4* __restrict__ fbk,
                        const float4* __restrict__ errsum, const float* __restrict__ fs,
                        float* __restrict__ out)
{
    const long long n4 = MD / 4;
    long long i = (long long)blockIdx.x * blockDim.x + threadIdx.x;
    float4* o4 = (float4*)out;
    if (i < n4) {
        o4[i] = cur[i];
    } else if (i < 2 * n4) {
        o4[i] = fbk[i - n4];
    } else if (i < 3 * n4) {
        float4 e = errsum[i - 2 * n4];
        o4[i] = make_float4(e.x * (1.f/3.f), e.y * (1.f/3.f),
                            e.z * (1.f/3.f), e.w * (1.f/3.f));
    }
    if (i < NCOL) out[3 * MD + i] = fs[i];
}

extern "C" void kernel_launch(void* const* d_in, const int* in_sizes, int n_in,
                              void* d_out, int out_size)
{
    const float* hs  = (const float*)d_in[0];
    const float* bu  = (const float*)d_in[1];
    const float* cbW = (const float*)d_in[2];
    const float* cbB = (const float*)d_in[3];
    const float* p1W = (const float*)d_in[4];
    const float* p1b = (const float*)d_in[5];
    const float* p2W = (const float*)d_in[6];
    const float* p2b = (const float*)d_in[7];
    const float* e1W = (const float*)d_in[8];
    const float* e1b = (const float*)d_in[9];
    const float* e2W = (const float*)d_in[10];
    const float* e2b = (const float*)d_in[11];
    const float* gW  = (const float*)d_in[12];
    const float* gb  = (const float*)d_in[13];
    const float* fs  = (const float*)d_in[14];
    float* out = (float*)d_out;

    float *cur, *h1, *err, *errsum, *fb, *fbk, *gainb;
    cudaGetSymbolAddress((void**)&cur,    g_cur);
    cudaGetSymbolAddress((void**)&h1,     g_h1);
    cudaGetSymbolAddress((void**)&err,    g_err);
    cudaGetSymbolAddress((void**)&errsum, g_errsum);
    cudaGetSymbolAddress((void**)&fb,     g_fb);
    cudaGetSymbolAddress((void**)&fbk,    g_fbk);
    cudaGetSymbolAddress((void**)&gainb,  g_gain);

    const long long n4 = MD / 4;
    init_k<<<(unsigned)((n4 + 255) / 256), 256>>>((const float4*)hs, (float4*)cur,
                                                  (float4*)errsum, n4);

    dim3 gP1(DIM2 / 128, MROWS / 128, 1);    // 16 x 224
    dim3 gD (DIM  / 128, MROWS / 128, 1);    //  8 x 224
    dim3 gCB(DIM  / 128, BATCH / 128, NCOL); //  8 x 32 x 7

    for (int it = 0; it < NITER; it++) {
        // h1 = gelu(cur @ p1_W^T + p1_b)            [M,2048]
        gemm_tc<EPI_GELU><<<gP1, 256>>>(cur, cur, DIM, DIM, p1W, p1b, h1, DIM2, DIM,
                                        0, 0, 0, 0, nullptr, nullptr, nullptr, nullptr);
        // err = bu - (h1 @ p2_W^T + p2_b); errsum += err
        gemm_tc<EPI_ERR><<<gD, 256>>>(h1, h1, DIM2, DIM2, p2W, p2b, err, DIM, DIM2,
                                      0, 0, 0, 0, bu, errsum, nullptr, nullptr);
        // fb[:,j,:] = cur[:,j,:] @ cb_W[j]^T + cb_b[j]   (z-batched over colony)
        gemm_tc<EPI_BIAS><<<gCB, 256>>>(cur, cur, DIM, NCOL * DIM, cbW, cbB,
                                        fb, NCOL * DIM, DIM,
                                        (long long)DIM, (long long)DIM * DIM,
                                        (long long)DIM, (long long)DIM,
                                        nullptr, nullptr, nullptr, nullptr);
        // feedback = rowsum(fb) - fb   (Fano mask == ones - I)
        feedback_k<<<(unsigned)(((long long)BATCH * DIM / 4 + 255) / 256), 256>>>(fb, fbk);
        // gain = sigmoid([cur|fbk] @ g_W^T + g_b)   (virtual concat over K)
        gemm_tc<EPI_SIG><<<gD, 256>>>(cur, fbk, DIM, DIM, gW, gb, gainb, DIM, DIM2,
                                      0, 0, 0, 0, nullptr, nullptr, nullptr, nullptr);
        // pe1 = gelu(err @ e1_W^T + e1_b)  (reuse h1 as [M,1024] scratch)
        gemm_tc<EPI_GELU><<<gD, 256>>>(err, err, DIM, DIM, e1W, e1b, h1, DIM, DIM,
                                       0, 0, 0, 0, nullptr, nullptr, nullptr, nullptr);
        // cur += (pe1 @ e2_W^T + e2_b) * gain * fs[c] * (5/3)
        gemm_tc<EPI_UPD><<<gD, 256>>>(h1, h1, DIM, DIM, e2W, e2b, cur, DIM, DIM,
                                      0, 0, 0, 0, nullptr, nullptr, gainb, fs);
    }

    final_k<<<(unsigned)((3 * n4 + 255) / 256), 256>>>((const float4*)cur,
                                                       (const float4*)fbk,
                                                       (const float4*)errsum, fs, out);
}